// round 3
// baseline (speedup 1.0000x reference)
#include <cuda_runtime.h>
#include <math.h>

// Problem constants
#define NN   2000
#define CC   4
#define LL   5000
#define EE   64000
#define HH   512
#define RP   207
#define L2O  1248          // (5000-11)/4+1
#define TILE_T 128
#define PMAX (4*TILE_T+8)  // 520 floats per channel row (16B-aligned rows)

// ---------------- scratch (device globals; no runtime allocation) ------------
__device__ float g_feat[NN*RP];
__device__ float g_h  [NN*HH];   // feat @ gcn_w
__device__ float g_z  [NN*HH];   // agg, then tanh(agg+b)
__device__ float g_g  [NN*HH];   // sigmoid(z@gate_w+b)
__device__ float g_xl [NN*HH];   // feat@lin_w+b
__device__ float g_deg [NN];
__device__ float g_dinv[NN];
__device__ float g_colsum[HH];
__device__ float g_colsq [HH];
__device__ float g_scale [HH];
__device__ float g_shift [HH];

// ---------------- fused conv pipeline: x -> feat (per-node block) ------------
__global__ __launch_bounds__(256)
void conv_feat_kernel(const float* __restrict__ x,
                      const float* __restrict__ w1, const float* __restrict__ b1,
                      const float* __restrict__ w2, const float* __restrict__ b2,
                      const float* __restrict__ w3, const float* __restrict__ b3)
{
    __shared__ float sw1[16][4];
    __shared__ float sb1[16];
    __shared__ float sw2[4][4][11];
    __shared__ float sb2[4];
    __shared__ float sw3[4][11];
    __shared__ float sb3;
    __shared__ __align__(16) float h2s[4][PMAX];  // stage-1 output tile (16B-aligned rows)
    __shared__ __align__(16) float y2s[4][L2O];   // full stage-2 output

    const int n   = blockIdx.x;
    const int tid = threadIdx.x;

    if (tid < 64)  sw1[tid >> 2][tid & 3] = w1[tid];
    if (tid < 16)  sb1[tid] = b1[tid];
    if (tid < 176) sw2[tid/44][(tid/11)&3][tid%11] = w2[tid];
    if (tid < 4)   sb2[tid] = b2[tid];
    if (tid < 44)  sw3[tid/11][tid%11] = w3[tid];
    if (tid == 0)  sb3 = b3[0];
    __syncthreads();

    const float* xn = x + (size_t)n * CC * LL;

    for (int t0 = 0; t0 < L2O; t0 += TILE_T) {
        const int Tt = min(TILE_T, L2O - t0);
        const int P  = 4*Tt + 7;

        // stage 1: 1x1 conv (4->16) + relu + group-of-4 max, fused
        for (int idx = tid; idx < P; idx += 256) {
            const int p = 4*t0 + idx;
            const float x0 = xn[p];
            const float x1 = xn[LL   + p];
            const float x2 = xn[2*LL + p];
            const float x3 = xn[3*LL + p];
            #pragma unroll
            for (int a = 0; a < 4; a++) {
                float mx = -3.4e38f;
                #pragma unroll
                for (int b = 0; b < 4; b++) {
                    const int o = a*4 + b;
                    float pre = sb1[o];
                    pre = fmaf(x0, sw1[o][0], pre);
                    pre = fmaf(x1, sw1[o][1], pre);
                    pre = fmaf(x2, sw1[o][2], pre);
                    pre = fmaf(x3, sw1[o][3], pre);
                    mx = fmaxf(mx, pre);
                }
                h2s[a][idx] = fmaxf(mx, 0.f);   // max(relu(..)) == relu(max(..))
            }
        }
        __syncthreads();

        // stage 2: conv (4->4, k=11, stride 4) + relu  — float4 smem reads
        for (int tt = tid; tt < Tt; tt += 256) {
            float acc0 = sb2[0], acc1 = sb2[1], acc2 = sb2[2], acc3 = sb2[3];
            #pragma unroll
            for (int c = 0; c < 4; c++) {
                const float4 v0 = *(const float4*)&h2s[c][4*tt];
                const float4 v1 = *(const float4*)&h2s[c][4*tt + 4];
                const float4 v2 = *(const float4*)&h2s[c][4*tt + 8];
                float hv[11] = {v0.x, v0.y, v0.z, v0.w,
                                v1.x, v1.y, v1.z, v1.w,
                                v2.x, v2.y, v2.z};
                #pragma unroll
                for (int k = 0; k < 11; k++) {
                    acc0 = fmaf(hv[k], sw2[0][c][k], acc0);
                    acc1 = fmaf(hv[k], sw2[1][c][k], acc1);
                    acc2 = fmaf(hv[k], sw2[2][c][k], acc2);
                    acc3 = fmaf(hv[k], sw2[3][c][k], acc3);
                }
            }
            y2s[0][t0+tt] = fmaxf(acc0, 0.f);
            y2s[1][t0+tt] = fmaxf(acc1, 0.f);
            y2s[2][t0+tt] = fmaxf(acc2, 0.f);
            y2s[3][t0+tt] = fmaxf(acc3, 0.f);
        }
        __syncthreads();
    }

    // stage 3: conv (4->1, k=11, stride 6) + relu -> feat
    for (int t = tid; t < RP; t += 256) {
        float acc = sb3;
        #pragma unroll
        for (int c = 0; c < 4; c++)
            #pragma unroll
            for (int k = 0; k < 11; k++)
                acc = fmaf(y2s[c][6*t + k], sw3[c][k], acc);
        g_feat[(size_t)n*RP + t] = fmaxf(acc, 0.f);
    }
}

// ---------------- GCN degree / norm ------------------------------------------
__global__ void deg_init_kernel() {
    int i = blockIdx.x*blockDim.x + threadIdx.x;
    if (i < NN) g_deg[i] = 1.0f;                 // self loop
}
__global__ void deg_count_kernel(const int* __restrict__ dst) {
    int e = blockIdx.x*blockDim.x + threadIdx.x;
    if (e < EE) atomicAdd(&g_deg[dst[e]], 1.0f);
}
__global__ void dinv_kernel() {
    int i = blockIdx.x*blockDim.x + threadIdx.x;
    if (i < NN) g_dinv[i] = rsqrtf(g_deg[i]);
}

// ---------------- generic tiled fp32 GEMM: C = act(A@B + bias) ----------------
// act: 0 = identity, 1 = sigmoid
__global__ __launch_bounds__(256)
void gemm_kernel(const float* __restrict__ A, const float* __restrict__ B,
                 const float* __restrict__ bias, float* __restrict__ C,
                 int M, int K, int Nc, int act)
{
    __shared__ float As[16][64+4];
    __shared__ float Bs[16][64+4];
    const int tid = threadIdx.x;
    const int tx = tid & 15, ty = tid >> 4;
    const int m0 = blockIdx.y * 64;
    const int n0 = blockIdx.x * 64;
    float acc[4][4] = {};

    for (int k0 = 0; k0 < K; k0 += 16) {
        {   // A tile 64x16  (As[k][m])
            const int c = tid & 15;        // k
            const int r0 = tid >> 4;       // m base
            #pragma unroll
            for (int i = 0; i < 4; i++) {
                const int r = r0 + i*16;
                const int gm = m0 + r, gk = k0 + c;
                As[c][r] = (gm < M && gk < K) ? A[(size_t)gm*K + gk] : 0.f;
            }
        }
        {   // B tile 16x64
            const int c = tid & 63;
            const int r0 = tid >> 6;       // 0..3
            #pragma unroll
            for (int i = 0; i < 4; i++) {
                const int r = r0 + i*4;
                const int gk = k0 + r, gn = n0 + c;
                Bs[r][c] = (gk < K && gn < Nc) ? B[(size_t)gk*Nc + gn] : 0.f;
            }
        }
        __syncthreads();
        #pragma unroll
        for (int k = 0; k < 16; k++) {
            float a[4], b[4];
            #pragma unroll
            for (int i = 0; i < 4; i++) a[i] = As[k][ty*4 + i];
            #pragma unroll
            for (int j = 0; j < 4; j++) b[j] = Bs[k][tx*4 + j];
            #pragma unroll
            for (int i = 0; i < 4; i++)
                #pragma unroll
                for (int j = 0; j < 4; j++)
                    acc[i][j] = fmaf(a[i], b[j], acc[i][j]);
        }
        __syncthreads();
    }

    #pragma unroll
    for (int i = 0; i < 4; i++) {
        const int gm = m0 + ty*4 + i;
        if (gm >= M) continue;
        #pragma unroll
        for (int j = 0; j < 4; j++) {
            const int gn = n0 + tx*4 + j;
            if (gn >= Nc) continue;
            float v = acc[i][j];
            if (bias) v += bias[gn];
            if (act == 1) v = 1.f / (1.f + expf(-v));
            C[(size_t)gm*Nc + gn] = v;
        }
    }
}

// ---------------- GCN aggregation --------------------------------------------
__global__ void gcn_self_kernel() {
    int i = blockIdx.x*blockDim.x + threadIdx.x;
    if (i < NN*HH) {
        const int n = i >> 9;
        const float dv = g_dinv[n];
        g_z[i] = g_h[i] * dv * dv;      // self-loop term
    }
}

__global__ __launch_bounds__(256)
void gcn_scatter_kernel(const int* __restrict__ src, const int* __restrict__ dst) {
    const int warp = (blockIdx.x * blockDim.x + threadIdx.x) >> 5;
    const int lane = threadIdx.x & 31;
    if (warp >= EE) return;
    const int s = src[warp], d = dst[warp];
    const float nrm = g_dinv[s] * g_dinv[d];
    const float4* hs = (const float4*)(g_h + (size_t)s * HH);
    float* ad = g_z + (size_t)d * HH;
    #pragma unroll
    for (int r = 0; r < 4; r++) {
        const int j = r*32 + lane;            // 0..127 float4s
        const float4 v = hs[j];
        atomicAdd(&ad[4*j + 0], v.x * nrm);
        atomicAdd(&ad[4*j + 1], v.y * nrm);
        atomicAdd(&ad[4*j + 2], v.z * nrm);
        atomicAdd(&ad[4*j + 3], v.w * nrm);
    }
}

__global__ void tanh_bias_kernel(const float* __restrict__ gcn_b) {
    int i = blockIdx.x*blockDim.x + threadIdx.x;
    if (i < NN*HH) g_z[i] = tanhf(g_z[i] + gcn_b[i & (HH-1)]);
}

// ---------------- gate combine + batchnorm -----------------------------------
__global__ void combine_kernel(float* __restrict__ out) {
    int i = blockIdx.x*blockDim.x + threadIdx.x;
    if (i < NN*HH) {
        const float gv = g_g[i];
        const float xl = g_xl[i];
        // (1-g)*xl + g*z = xl + g*(z-xl)
        out[i] = fmaxf(fmaf(gv, g_z[i] - xl, xl), 0.f);
    }
}

__global__ void bn_zero_kernel() {
    int i = blockIdx.x*blockDim.x + threadIdx.x;
    if (i < HH) { g_colsum[i] = 0.f; g_colsq[i] = 0.f; }
}

__global__ __launch_bounds__(256)
void bn_stats_kernel(const float* __restrict__ out) {
    const int col = blockIdx.x*32 + (threadIdx.x & 31);
    const int r   = threadIdx.x >> 5;          // 0..7
    const int n0  = blockIdx.y * 250;
    float s = 0.f, q = 0.f;
    for (int n = n0 + r; n < n0 + 250; n += 8) {
        const float v = out[(size_t)n*HH + col];
        s += v; q += v*v;
    }
    atomicAdd(&g_colsum[col], s);
    atomicAdd(&g_colsq [col], q);
}

__global__ void bn_final_kernel(const float* __restrict__ gamma,
                                const float* __restrict__ beta) {
    int j = blockIdx.x*blockDim.x + threadIdx.x;
    if (j < HH) {
        const float inv_n = 1.f / (float)NN;
        const float mean = g_colsum[j] * inv_n;
        const float var  = g_colsq[j] * inv_n - mean*mean;
        const float sc = rsqrtf(var + 1e-5f) * gamma[j];
        g_scale[j] = sc;
        g_shift[j] = beta[j] - mean*sc;
    }
}

__global__ void bn_apply_kernel(float* __restrict__ out) {
    int i = blockIdx.x*blockDim.x + threadIdx.x;
    if (i < NN*HH) {
        const int j = i & (HH-1);
        out[i] = fmaf(out[i], g_scale[j], g_shift[j]);
    }
}

// ---------------- launch ------------------------------------------------------
extern "C" void kernel_launch(void* const* d_in, const int* in_sizes, int n_in,
                              void* d_out, int out_size)
{
    const float* x      = (const float*)d_in[0];
    const int*   eidx   = (const int*)  d_in[1];   // (2, E): [src | dst]
    const float* w1     = (const float*)d_in[2];
    const float* b1     = (const float*)d_in[3];
    const float* w2     = (const float*)d_in[4];
    const float* b2     = (const float*)d_in[5];
    const float* w3     = (const float*)d_in[6];
    const float* b3     = (const float*)d_in[7];
    const float* gcn_w  = (const float*)d_in[8];
    const float* gcn_b  = (const float*)d_in[9];
    const float* lin_w  = (const float*)d_in[10];
    const float* lin_b  = (const float*)d_in[11];
    const float* gate_w = (const float*)d_in[12];
    const float* gate_b = (const float*)d_in[13];
    const float* bn_g   = (const float*)d_in[14];
    const float* bn_b   = (const float*)d_in[15];
    float* out = (float*)d_out;

    const int* src = eidx;
    const int* dst = eidx + EE;

    // device-global scratch pointers (for GEMM arguments)
    float *p_feat, *p_h, *p_z, *p_g, *p_xl;
    cudaGetSymbolAddress((void**)&p_feat, g_feat);
    cudaGetSymbolAddress((void**)&p_h,    g_h);
    cudaGetSymbolAddress((void**)&p_z,    g_z);
    cudaGetSymbolAddress((void**)&p_g,    g_g);
    cudaGetSymbolAddress((void**)&p_xl,   g_xl);

    // 1) fused conv pipeline -> feat
    conv_feat_kernel<<<NN, 256>>>(x, w1, b1, w2, b2, w3, b3);

    // 2) degrees / norms
    deg_init_kernel <<<(NN+255)/256, 256>>>();
    deg_count_kernel<<<(EE+255)/256, 256>>>(dst);
    dinv_kernel     <<<(NN+255)/256, 256>>>();

    // 3) h = feat @ gcn_w
    gemm_kernel<<<dim3(HH/64, (NN+63)/64), 256>>>(p_feat, gcn_w, nullptr, p_h,
                                                  NN, RP, HH, 0);

    // 4) aggregate (self + edges), z = tanh(agg + b)
    gcn_self_kernel   <<<(NN*HH+255)/256, 256>>>();
    gcn_scatter_kernel<<<EE/8, 256>>>(src, dst);
    tanh_bias_kernel  <<<(NN*HH+255)/256, 256>>>(gcn_b);

    // 5) gate + linear branches
    gemm_kernel<<<dim3(HH/64, (NN+63)/64), 256>>>(p_z,    gate_w, gate_b, p_g,
                                                  NN, HH, HH, 1);
    gemm_kernel<<<dim3(HH/64, (NN+63)/64), 256>>>(p_feat, lin_w,  lin_b,  p_xl,
                                                  NN, RP, HH, 0);

    // 6) gated combine + relu
    combine_kernel<<<(NN*HH+255)/256, 256>>>(out);

    // 7) batchnorm over axis 0
    bn_zero_kernel <<<(HH+255)/256, 256>>>();
    bn_stats_kernel<<<dim3(HH/32, 8), 256>>>(out);
    bn_final_kernel<<<(HH+255)/256, 256>>>(bn_g, bn_b);
    bn_apply_kernel<<<(NN*HH+255)/256, 256>>>(out);
}

// round 4
// speedup vs baseline: 1.0393x; 1.0393x over previous
#include <cuda_runtime.h>
#include <math.h>

// Problem constants
#define NN   2000
#define CC   4
#define LL   5000
#define EE   64000
#define HH   512
#define RP   207
#define L2O  1248          // (5000-11)/4+1
#define TILE_T 128
#define PMAX (4*TILE_T+8)
#define KT   32            // GEMM k-tile

// ---------------- scratch (device globals; no runtime allocation) ------------
__device__ float g_feat[NN*RP];
__device__ float g_h  [NN*HH];   // feat @ gcn_w
__device__ float g_z  [NN*HH];   // self + scatter, then tanh(.+b)
__device__ float g_xl [NN*HH];   // feat@lin_w+b
__device__ float g_deg [NN];
__device__ float g_dinv[NN];
__device__ float g_colsum[HH];
__device__ float g_colsq [HH];
__device__ float g_scale [HH];
__device__ float g_shift [HH];

// ---------------- fused conv pipeline: x -> feat (per-node block) ------------
__global__ __launch_bounds__(256)
void conv_feat_kernel(const float* __restrict__ x,
                      const float* __restrict__ w1, const float* __restrict__ b1,
                      const float* __restrict__ w2, const float* __restrict__ b2,
                      const float* __restrict__ w3, const float* __restrict__ b3)
{
    __shared__ float sw1[16][4];
    __shared__ float sb1[16];
    __shared__ float sw2[4][4][11];
    __shared__ float sb2[4];
    __shared__ float sw3[4][11];
    __shared__ float sb3;
    __shared__ __align__(16) float h2s[4][PMAX];
    __shared__ __align__(16) float y2s[4][L2O];

    const int n   = blockIdx.x;
    const int tid = threadIdx.x;

    if (tid < 64)  sw1[tid >> 2][tid & 3] = w1[tid];
    if (tid < 16)  sb1[tid] = b1[tid];
    if (tid < 176) sw2[tid/44][(tid/11)&3][tid%11] = w2[tid];
    if (tid < 4)   sb2[tid] = b2[tid];
    if (tid < 44)  sw3[tid/11][tid%11] = w3[tid];
    if (tid == 0)  sb3 = b3[0];
    __syncthreads();

    const float* xn = x + (size_t)n * CC * LL;

    for (int t0 = 0; t0 < L2O; t0 += TILE_T) {
        const int Tt = min(TILE_T, L2O - t0);
        const int P  = 4*Tt + 7;

        // stage 1: 1x1 conv (4->16) + relu + group-of-4 max
        for (int idx = tid; idx < P; idx += 256) {
            const int p = 4*t0 + idx;
            const float x0 = xn[p];
            const float x1 = xn[LL   + p];
            const float x2 = xn[2*LL + p];
            const float x3 = xn[3*LL + p];
            #pragma unroll
            for (int a = 0; a < 4; a++) {
                float mx = -3.4e38f;
                #pragma unroll
                for (int b = 0; b < 4; b++) {
                    const int o = a*4 + b;
                    float pre = sb1[o];
                    pre = fmaf(x0, sw1[o][0], pre);
                    pre = fmaf(x1, sw1[o][1], pre);
                    pre = fmaf(x2, sw1[o][2], pre);
                    pre = fmaf(x3, sw1[o][3], pre);
                    mx = fmaxf(mx, pre);
                }
                h2s[a][idx] = fmaxf(mx, 0.f);
            }
        }
        __syncthreads();

        // stage 2: conv (4->4, k=11, stride 4) + relu
        for (int tt = tid; tt < Tt; tt += 256) {
            float acc0 = sb2[0], acc1 = sb2[1], acc2 = sb2[2], acc3 = sb2[3];
            #pragma unroll
            for (int c = 0; c < 4; c++) {
                const float4 v0 = *(const float4*)&h2s[c][4*tt];
                const float4 v1 = *(const float4*)&h2s[c][4*tt + 4];
                const float4 v2 = *(const float4*)&h2s[c][4*tt + 8];
                float hv[11] = {v0.x, v0.y, v0.z, v0.w,
                                v1.x, v1.y, v1.z, v1.w,
                                v2.x, v2.y, v2.z};
                #pragma unroll
                for (int k = 0; k < 11; k++) {
                    acc0 = fmaf(hv[k], sw2[0][c][k], acc0);
                    acc1 = fmaf(hv[k], sw2[1][c][k], acc1);
                    acc2 = fmaf(hv[k], sw2[2][c][k], acc2);
                    acc3 = fmaf(hv[k], sw2[3][c][k], acc3);
                }
            }
            y2s[0][t0+tt] = fmaxf(acc0, 0.f);
            y2s[1][t0+tt] = fmaxf(acc1, 0.f);
            y2s[2][t0+tt] = fmaxf(acc2, 0.f);
            y2s[3][t0+tt] = fmaxf(acc3, 0.f);
        }
        __syncthreads();
    }

    // stage 3: conv (4->1, k=11, stride 6) + relu -> feat
    for (int t = tid; t < RP; t += 256) {
        float acc = sb3;
        #pragma unroll
        for (int c = 0; c < 4; c++)
            #pragma unroll
            for (int k = 0; k < 11; k++)
                acc = fmaf(y2s[c][6*t + k], sw3[c][k], acc);
        g_feat[(size_t)n*RP + t] = fmaxf(acc, 0.f);
    }
}

// ---------------- GCN degree / norm (deg_init also zeroes BN accumulators) ---
__global__ void deg_init_kernel() {
    int i = blockIdx.x*blockDim.x + threadIdx.x;
    if (i < NN) g_deg[i] = 1.0f;
    if (i < HH) { g_colsum[i] = 0.f; g_colsq[i] = 0.f; }
}
__global__ void deg_count_kernel(const int* __restrict__ dst) {
    int e = blockIdx.x*blockDim.x + threadIdx.x;
    if (e < EE) atomicAdd(&g_deg[dst[e]], 1.0f);
}
__global__ void dinv_kernel() {
    int i = blockIdx.x*blockDim.x + threadIdx.x;
    if (i < NN) g_dinv[i] = rsqrtf(g_deg[i]);
}

// ---------------- dual GEMM: h = feat@gcn_w ; xl = feat@lin_w + b -------------
// Epilogue: g_h = h ; g_z = h * dinv[m]^2 (self-loop term) ; g_xl = xl + lin_b
__global__ __launch_bounds__(256)
void dual_gemm_kernel(const float* __restrict__ A,
                      const float* __restrict__ B1, const float* __restrict__ B2,
                      const float* __restrict__ lin_b)
{
    __shared__ __align__(16) float As [KT][68];
    __shared__ __align__(16) float Bs1[KT][68];
    __shared__ __align__(16) float Bs2[KT][68];
    const int tid = threadIdx.x;
    const int tx = tid & 15, ty = tid >> 4;
    const int m0 = blockIdx.y * 64;
    const int n0 = blockIdx.x * 64;
    const int M = NN, K = RP;

    float accH[4][4] = {};
    float accX[4][4] = {};

    for (int k0 = 0; k0 < K; k0 += KT) {
        // A tile 64m x 32k, transposed into As[k][m]; scalar coalesced loads
        #pragma unroll
        for (int p = 0; p < 8; p++) {
            const int idx = tid + p*256;
            const int m = idx >> 5, k = idx & 31;
            const int gm = m0 + m, gk = k0 + k;
            As[k][m] = (gm < M && gk < K) ? A[(size_t)gm*K + gk] : 0.f;
        }
        // B tiles 32k x 64n, float4 loads
        {
            const int r = tid >> 4, q = tid & 15;
            #pragma unroll
            for (int p = 0; p < 2; p++) {
                const int k = r + p*16;
                const int gk = k0 + k;
                float4 v1 = make_float4(0.f,0.f,0.f,0.f), v2 = v1;
                if (gk < K) {
                    v1 = *(const float4*)&B1[(size_t)gk*HH + n0 + q*4];
                    v2 = *(const float4*)&B2[(size_t)gk*HH + n0 + q*4];
                }
                *(float4*)&Bs1[k][q*4] = v1;
                *(float4*)&Bs2[k][q*4] = v2;
            }
        }
        __syncthreads();
        #pragma unroll
        for (int k = 0; k < KT; k++) {
            const float4 av = *(const float4*)&As [k][ty*4];
            const float4 b1 = *(const float4*)&Bs1[k][tx*4];
            const float4 b2 = *(const float4*)&Bs2[k][tx*4];
            const float a[4] = {av.x, av.y, av.z, av.w};
            const float p[4] = {b1.x, b1.y, b1.z, b1.w};
            const float q[4] = {b2.x, b2.y, b2.z, b2.w};
            #pragma unroll
            for (int i = 0; i < 4; i++)
                #pragma unroll
                for (int j = 0; j < 4; j++) {
                    accH[i][j] = fmaf(a[i], p[j], accH[i][j]);
                    accX[i][j] = fmaf(a[i], q[j], accX[i][j]);
                }
        }
        __syncthreads();
    }

    #pragma unroll
    for (int i = 0; i < 4; i++) {
        const int gm = m0 + ty*4 + i;
        if (gm >= M) continue;
        const float dv = g_dinv[gm];
        const float dv2 = dv * dv;
        #pragma unroll
        for (int j = 0; j < 4; j++) {
            const int gn = n0 + tx*4 + j;
            const float h = accH[i][j];
            g_h [(size_t)gm*HH + gn] = h;
            g_z [(size_t)gm*HH + gn] = h * dv2;
            g_xl[(size_t)gm*HH + gn] = accX[i][j] + lin_b[gn];
        }
    }
}

// ---------------- GCN scatter -------------------------------------------------
__global__ __launch_bounds__(256)
void gcn_scatter_kernel(const int* __restrict__ src, const int* __restrict__ dst) {
    const int warp = (blockIdx.x * blockDim.x + threadIdx.x) >> 5;
    const int lane = threadIdx.x & 31;
    if (warp >= EE) return;
    const int s = src[warp], d = dst[warp];
    const float nrm = g_dinv[s] * g_dinv[d];
    const float4* hs = (const float4*)(g_h + (size_t)s * HH);
    float* ad = g_z + (size_t)d * HH;
    #pragma unroll
    for (int r = 0; r < 4; r++) {
        const int j = r*32 + lane;
        const float4 v = hs[j];
        atomicAdd(&ad[4*j + 0], v.x * nrm);
        atomicAdd(&ad[4*j + 1], v.y * nrm);
        atomicAdd(&ad[4*j + 2], v.z * nrm);
        atomicAdd(&ad[4*j + 3], v.w * nrm);
    }
}

__global__ void tanh_bias_kernel(const float* __restrict__ gcn_b) {
    int i = blockIdx.x*blockDim.x + threadIdx.x;
    if (i < NN*HH) g_z[i] = tanhf(g_z[i] + gcn_b[i & (HH-1)]);
}

// ---------------- gate GEMM + combine + BN partial stats ----------------------
// g = sigmoid(z@gate_w + b) ; out = relu(xl + g*(z-xl)) ; accumulate col sums
__global__ __launch_bounds__(256)
void gate_gemm_kernel(const float* __restrict__ A,     // g_z (tanh'd)
                      const float* __restrict__ B,     // gate_w
                      const float* __restrict__ bias,  // gate_b
                      float* __restrict__ out)
{
    __shared__ __align__(16) float As[KT][68];
    __shared__ __align__(16) float Bs[KT][68];
    __shared__ float redS[16][64];
    __shared__ float redQ[16][64];
    const int tid = threadIdx.x;
    const int tx = tid & 15, ty = tid >> 4;
    const int m0 = blockIdx.y * 64;
    const int n0 = blockIdx.x * 64;
    const int M = NN, K = HH;

    float acc[4][4] = {};

    for (int k0 = 0; k0 < K; k0 += KT) {
        #pragma unroll
        for (int p = 0; p < 8; p++) {
            const int idx = tid + p*256;
            const int m = idx >> 5, k = idx & 31;
            const int gm = m0 + m;
            As[k][m] = (gm < M) ? A[(size_t)gm*K + k0 + k] : 0.f;
        }
        {
            const int r = tid >> 4, q = tid & 15;
            #pragma unroll
            for (int p = 0; p < 2; p++) {
                const int k = r + p*16;
                *(float4*)&Bs[k][q*4] =
                    *(const float4*)&B[(size_t)(k0+k)*HH + n0 + q*4];
            }
        }
        __syncthreads();
        #pragma unroll
        for (int k = 0; k < KT; k++) {
            const float4 av = *(const float4*)&As[k][ty*4];
            const float4 bv = *(const float4*)&Bs[k][tx*4];
            const float a[4] = {av.x, av.y, av.z, av.w};
            const float b[4] = {bv.x, bv.y, bv.z, bv.w};
            #pragma unroll
            for (int i = 0; i < 4; i++)
                #pragma unroll
                for (int j = 0; j < 4; j++)
                    acc[i][j] = fmaf(a[i], b[j], acc[i][j]);
        }
        __syncthreads();
    }

    // epilogue: sigmoid gate, combine with z/xl, relu, write out; BN partials
    float cs[4] = {0.f,0.f,0.f,0.f};
    float cq[4] = {0.f,0.f,0.f,0.f};
    #pragma unroll
    for (int i = 0; i < 4; i++) {
        const int gm = m0 + ty*4 + i;
        if (gm >= M) continue;
        #pragma unroll
        for (int j = 0; j < 4; j++) {
            const int gn = n0 + tx*4 + j;
            const float g  = 1.f / (1.f + expf(-(acc[i][j] + bias[gn])));
            const float z  = A   [(size_t)gm*HH + gn];
            const float xl = g_xl[(size_t)gm*HH + gn];
            const float o  = fmaxf(fmaf(g, z - xl, xl), 0.f);
            out[(size_t)gm*HH + gn] = o;
            cs[j] += o;
            cq[j] += o*o;
        }
    }
    #pragma unroll
    for (int j = 0; j < 4; j++) {
        redS[ty][tx*4+j] = cs[j];
        redQ[ty][tx*4+j] = cq[j];
    }
    __syncthreads();
    if (tid < 64) {
        float s = 0.f, q = 0.f;
        #pragma unroll
        for (int r = 0; r < 16; r++) { s += redS[r][tid]; q += redQ[r][tid]; }
        atomicAdd(&g_colsum[n0 + tid], s);
        atomicAdd(&g_colsq [n0 + tid], q);
    }
}

// ---------------- batchnorm ----------------------------------------------------
__global__ void bn_final_kernel(const float* __restrict__ gamma,
                                const float* __restrict__ beta) {
    int j = blockIdx.x*blockDim.x + threadIdx.x;
    if (j < HH) {
        const float inv_n = 1.f / (float)NN;
        const float mean = g_colsum[j] * inv_n;
        const float var  = g_colsq[j] * inv_n - mean*mean;
        const float sc = rsqrtf(var + 1e-5f) * gamma[j];
        g_scale[j] = sc;
        g_shift[j] = beta[j] - mean*sc;
    }
}

__global__ void bn_apply_kernel(float* __restrict__ out) {
    int i = blockIdx.x*blockDim.x + threadIdx.x;
    if (i < NN*HH) {
        const int j = i & (HH-1);
        out[i] = fmaf(out[i], g_scale[j], g_shift[j]);
    }
}

// ---------------- launch ------------------------------------------------------
extern "C" void kernel_launch(void* const* d_in, const int* in_sizes, int n_in,
                              void* d_out, int out_size)
{
    const float* x      = (const float*)d_in[0];
    const int*   eidx   = (const int*)  d_in[1];
    const float* w1     = (const float*)d_in[2];
    const float* b1     = (const float*)d_in[3];
    const float* w2     = (const float*)d_in[4];
    const float* b2     = (const float*)d_in[5];
    const float* w3     = (const float*)d_in[6];
    const float* b3     = (const float*)d_in[7];
    const float* gcn_w  = (const float*)d_in[8];
    const float* gcn_b  = (const float*)d_in[9];
    const float* lin_w  = (const float*)d_in[10];
    const float* lin_b  = (const float*)d_in[11];
    const float* gate_w = (const float*)d_in[12];
    const float* gate_b = (const float*)d_in[13];
    const float* bn_g   = (const float*)d_in[14];
    const float* bn_b   = (const float*)d_in[15];
    float* out = (float*)d_out;

    const int* src = eidx;
    const int* dst = eidx + EE;

    float *p_feat, *p_z;
    cudaGetSymbolAddress((void**)&p_feat, g_feat);
    cudaGetSymbolAddress((void**)&p_z,    g_z);

    // 1) fused conv pipeline -> feat
    conv_feat_kernel<<<NN, 256>>>(x, w1, b1, w2, b2, w3, b3);

    // 2-4) degrees / norms (+ zero BN accumulators)
    deg_init_kernel <<<(NN+255)/256, 256>>>();
    deg_count_kernel<<<(EE+255)/256, 256>>>(dst);
    dinv_kernel     <<<(NN+255)/256, 256>>>();

    // 5) dual GEMM: h = feat@gcn_w (also self term into z), xl = feat@lin_w+b
    dual_gemm_kernel<<<dim3(HH/64, (NN+63)/64), 256>>>(p_feat, gcn_w, lin_w, lin_b);

    // 6) edge scatter into z
    gcn_scatter_kernel<<<EE/8, 256>>>(src, dst);

    // 7) z = tanh(z + gcn_b)
    tanh_bias_kernel<<<(NN*HH+255)/256, 256>>>(gcn_b);

    // 8) gate GEMM + combine + relu + BN partial stats
    gate_gemm_kernel<<<dim3(HH/64, (NN+63)/64), 256>>>(p_z, gate_w, gate_b, out);

    // 9-10) batchnorm finalize + apply
    bn_final_kernel<<<(HH+255)/256, 256>>>(bn_g, bn_b);
    bn_apply_kernel<<<(NN*HH+255)/256, 256>>>(out);
}

// round 5
// speedup vs baseline: 1.2369x; 1.1901x over previous
#include <cuda_runtime.h>
#include <math.h>

// Problem constants
#define NN   2000
#define CC   4
#define LL   5000
#define EE   64000
#define HH   512
#define RP   207
#define L2O  1248          // (5000-11)/4+1
#define TILE_T 128
#define PMAX (4*TILE_T+8)
#define KT   32            // GEMM k-tile

// ---------------- scratch (device globals; no runtime allocation) ------------
__device__ float g_feat[NN*RP];
__device__ float g_h  [NN*HH];   // feat @ gcn_w
__device__ float g_z  [NN*HH];   // tanh(agg + b)
__device__ float g_xl [NN*HH];   // feat@lin_w+b
__device__ int   g_cnt [NN];     // in-degree (excl self)
__device__ int   g_off [NN];     // CSR offsets
__device__ int   g_cur [NN];     // fill cursors
__device__ int   g_esrc[EE];     // CSR: src node per edge slot
__device__ float g_dinv[NN];
__device__ float g_colsum[HH];
__device__ float g_colsq [HH];
__device__ float g_scale [HH];
__device__ float g_shift [HH];

// ---------------- fused conv pipeline: x -> feat (per-node block) ------------
__global__ __launch_bounds__(256)
void conv_feat_kernel(const float* __restrict__ x,
                      const float* __restrict__ w1, const float* __restrict__ b1,
                      const float* __restrict__ w2, const float* __restrict__ b2,
                      const float* __restrict__ w3, const float* __restrict__ b3)
{
    __shared__ float sw1[16][4];
    __shared__ float sb1[16];
    __shared__ float sw2[4][4][11];
    __shared__ float sb2[4];
    __shared__ float sw3[4][11];
    __shared__ float sb3;
    __shared__ __align__(16) float h2s[4][PMAX];
    __shared__ __align__(16) float y2s[4][L2O];

    const int n   = blockIdx.x;
    const int tid = threadIdx.x;

    if (tid < 64)  sw1[tid >> 2][tid & 3] = w1[tid];
    if (tid < 16)  sb1[tid] = b1[tid];
    if (tid < 176) sw2[tid/44][(tid/11)&3][tid%11] = w2[tid];
    if (tid < 4)   sb2[tid] = b2[tid];
    if (tid < 44)  sw3[tid/11][tid%11] = w3[tid];
    if (tid == 0)  sb3 = b3[0];
    __syncthreads();

    const float* xn = x + (size_t)n * CC * LL;

    for (int t0 = 0; t0 < L2O; t0 += TILE_T) {
        const int Tt = min(TILE_T, L2O - t0);
        const int P  = 4*Tt + 7;

        // stage 1: 1x1 conv (4->16) + relu + group-of-4 max
        for (int idx = tid; idx < P; idx += 256) {
            const int p = 4*t0 + idx;
            const float x0 = xn[p];
            const float x1 = xn[LL   + p];
            const float x2 = xn[2*LL + p];
            const float x3 = xn[3*LL + p];
            #pragma unroll
            for (int a = 0; a < 4; a++) {
                float mx = -3.4e38f;
                #pragma unroll
                for (int b = 0; b < 4; b++) {
                    const int o = a*4 + b;
                    float pre = sb1[o];
                    pre = fmaf(x0, sw1[o][0], pre);
                    pre = fmaf(x1, sw1[o][1], pre);
                    pre = fmaf(x2, sw1[o][2], pre);
                    pre = fmaf(x3, sw1[o][3], pre);
                    mx = fmaxf(mx, pre);
                }
                h2s[a][idx] = fmaxf(mx, 0.f);
            }
        }
        __syncthreads();

        // stage 2: conv (4->4, k=11, stride 4) + relu
        for (int tt = tid; tt < Tt; tt += 256) {
            float acc0 = sb2[0], acc1 = sb2[1], acc2 = sb2[2], acc3 = sb2[3];
            #pragma unroll
            for (int c = 0; c < 4; c++) {
                const float4 v0 = *(const float4*)&h2s[c][4*tt];
                const float4 v1 = *(const float4*)&h2s[c][4*tt + 4];
                const float4 v2 = *(const float4*)&h2s[c][4*tt + 8];
                float hv[11] = {v0.x, v0.y, v0.z, v0.w,
                                v1.x, v1.y, v1.z, v1.w,
                                v2.x, v2.y, v2.z};
                #pragma unroll
                for (int k = 0; k < 11; k++) {
                    acc0 = fmaf(hv[k], sw2[0][c][k], acc0);
                    acc1 = fmaf(hv[k], sw2[1][c][k], acc1);
                    acc2 = fmaf(hv[k], sw2[2][c][k], acc2);
                    acc3 = fmaf(hv[k], sw2[3][c][k], acc3);
                }
            }
            y2s[0][t0+tt] = fmaxf(acc0, 0.f);
            y2s[1][t0+tt] = fmaxf(acc1, 0.f);
            y2s[2][t0+tt] = fmaxf(acc2, 0.f);
            y2s[3][t0+tt] = fmaxf(acc3, 0.f);
        }
        __syncthreads();
    }

    // stage 3: conv (4->1, k=11, stride 6) + relu -> feat
    for (int t = tid; t < RP; t += 256) {
        float acc = sb3;
        #pragma unroll
        for (int c = 0; c < 4; c++)
            #pragma unroll
            for (int k = 0; k < 11; k++)
                acc = fmaf(y2s[c][6*t + k], sw3[c][k], acc);
        g_feat[(size_t)n*RP + t] = fmaxf(acc, 0.f);
    }
}

// ---------------- CSR build ---------------------------------------------------
__global__ void csr_init_kernel() {
    int i = blockIdx.x*blockDim.x + threadIdx.x;
    if (i < NN) g_cnt[i] = 0;
    if (i < HH) { g_colsum[i] = 0.f; g_colsq[i] = 0.f; }
}
__global__ void csr_count_kernel(const int* __restrict__ dst) {
    int e = blockIdx.x*blockDim.x + threadIdx.x;
    if (e < EE) atomicAdd(&g_cnt[dst[e]], 1);
}
// single-block exclusive scan of g_cnt (2000 ints); also dinv = rsqrt(cnt+1)
__global__ __launch_bounds__(256)
void csr_scan_kernel() {
    __shared__ int tsum[256];
    __shared__ int wsum[8];
    const int t = threadIdx.x;
    const int base = t * 8;
    int c[8], s = 0;
    #pragma unroll
    for (int i = 0; i < 8; i++) {
        const int n = base + i;
        c[i] = (n < NN) ? g_cnt[n] : 0;
        s += c[i];
    }
    tsum[t] = s;
    // warp inclusive scan of tsum
    int v = s;
    #pragma unroll
    for (int d = 1; d < 32; d <<= 1) {
        int u = __shfl_up_sync(0xffffffffu, v, d);
        if ((t & 31) >= d) v += u;
    }
    if ((t & 31) == 31) wsum[t >> 5] = v;
    __syncthreads();
    if (t < 8) {
        int w = wsum[t];
        #pragma unroll
        for (int d = 1; d < 8; d <<= 1) {
            int u = __shfl_up_sync(0xffu, w, d);
            if (t >= d) w += u;
        }
        wsum[t] = w;
    }
    __syncthreads();
    int excl = v - s + ((t >> 5) ? wsum[(t >> 5) - 1] : 0);  // exclusive prefix of this thread
    #pragma unroll
    for (int i = 0; i < 8; i++) {
        const int n = base + i;
        if (n < NN) {
            g_off[n] = excl;
            g_cur[n] = excl;
            g_dinv[n] = rsqrtf((float)(c[i] + 1));
        }
        excl += c[i];
    }
}
__global__ void csr_fill_kernel(const int* __restrict__ src, const int* __restrict__ dst) {
    int e = blockIdx.x*blockDim.x + threadIdx.x;
    if (e < EE) {
        const int p = atomicAdd(&g_cur[dst[e]], 1);
        g_esrc[p] = src[e];
    }
}

// ---------------- dual GEMM: h = feat@gcn_w ; xl = feat@lin_w + b -------------
__global__ __launch_bounds__(256)
void dual_gemm_kernel(const float* __restrict__ A,
                      const float* __restrict__ B1, const float* __restrict__ B2,
                      const float* __restrict__ lin_b)
{
    __shared__ __align__(16) float As [KT][68];
    __shared__ __align__(16) float Bs1[KT][68];
    __shared__ __align__(16) float Bs2[KT][68];
    const int tid = threadIdx.x;
    const int tx = tid & 15, ty = tid >> 4;
    const int m0 = blockIdx.y * 64;
    const int n0 = blockIdx.x * 64;
    const int M = NN, K = RP;

    float accH[4][4] = {};
    float accX[4][4] = {};

    for (int k0 = 0; k0 < K; k0 += KT) {
        #pragma unroll
        for (int p = 0; p < 8; p++) {
            const int idx = tid + p*256;
            const int m = idx >> 5, k = idx & 31;
            const int gm = m0 + m, gk = k0 + k;
            As[k][m] = (gm < M && gk < K) ? A[(size_t)gm*K + gk] : 0.f;
        }
        {
            const int r = tid >> 4, q = tid & 15;
            #pragma unroll
            for (int p = 0; p < 2; p++) {
                const int k = r + p*16;
                const int gk = k0 + k;
                float4 v1 = make_float4(0.f,0.f,0.f,0.f), v2 = v1;
                if (gk < K) {
                    v1 = *(const float4*)&B1[(size_t)gk*HH + n0 + q*4];
                    v2 = *(const float4*)&B2[(size_t)gk*HH + n0 + q*4];
                }
                *(float4*)&Bs1[k][q*4] = v1;
                *(float4*)&Bs2[k][q*4] = v2;
            }
        }
        __syncthreads();
        #pragma unroll
        for (int k = 0; k < KT; k++) {
            const float4 av = *(const float4*)&As [k][ty*4];
            const float4 b1 = *(const float4*)&Bs1[k][tx*4];
            const float4 b2 = *(const float4*)&Bs2[k][tx*4];
            const float a[4] = {av.x, av.y, av.z, av.w};
            const float p[4] = {b1.x, b1.y, b1.z, b1.w};
            const float q[4] = {b2.x, b2.y, b2.z, b2.w};
            #pragma unroll
            for (int i = 0; i < 4; i++)
                #pragma unroll
                for (int j = 0; j < 4; j++) {
                    accH[i][j] = fmaf(a[i], p[j], accH[i][j]);
                    accX[i][j] = fmaf(a[i], q[j], accX[i][j]);
                }
        }
        __syncthreads();
    }

    #pragma unroll
    for (int i = 0; i < 4; i++) {
        const int gm = m0 + ty*4 + i;
        if (gm >= M) continue;
        #pragma unroll
        for (int j = 0; j < 4; j++) {
            const int gn = n0 + tx*4 + j;
            g_h [(size_t)gm*HH + gn] = accH[i][j];
            g_xl[(size_t)gm*HH + gn] = accX[i][j] + lin_b[gn];
        }
    }
}

// ---------------- GCN gather (CSR) + tanh(+bias) ------------------------------
// block = dst node; thread owns 2 contiguous columns (float2)
#define ECH 128
__global__ __launch_bounds__(256)
void gcn_gather_kernel(const float* __restrict__ gcn_b)
{
    __shared__ int   s_src[ECH];
    __shared__ float s_w  [ECH];
    const int n = blockIdx.x;
    const int t = threadIdx.x;
    const float dn = g_dinv[n];
    const int off = g_off[n];
    const int cnt = g_cnt[n];

    // self-loop term
    const float2 hv0 = *(const float2*)&g_h[(size_t)n*HH + 2*t];
    float2 acc;
    acc.x = hv0.x * dn * dn;
    acc.y = hv0.y * dn * dn;

    for (int c0 = 0; c0 < cnt; c0 += ECH) {
        const int m = min(ECH, cnt - c0);
        __syncthreads();
        if (t < m) {
            const int s = g_esrc[off + c0 + t];
            s_src[t] = s;
            s_w[t]   = g_dinv[s] * dn;
        }
        __syncthreads();
        int j = 0;
        for (; j + 4 <= m; j += 4) {
            const int   s0 = s_src[j],   s1 = s_src[j+1], s2 = s_src[j+2], s3 = s_src[j+3];
            const float w0 = s_w[j],     w1 = s_w[j+1],   w2 = s_w[j+2],   w3 = s_w[j+3];
            const float2 h0 = *(const float2*)&g_h[(size_t)s0*HH + 2*t];
            const float2 h1 = *(const float2*)&g_h[(size_t)s1*HH + 2*t];
            const float2 h2 = *(const float2*)&g_h[(size_t)s2*HH + 2*t];
            const float2 h3 = *(const float2*)&g_h[(size_t)s3*HH + 2*t];
            acc.x = fmaf(w0, h0.x, acc.x); acc.y = fmaf(w0, h0.y, acc.y);
            acc.x = fmaf(w1, h1.x, acc.x); acc.y = fmaf(w1, h1.y, acc.y);
            acc.x = fmaf(w2, h2.x, acc.x); acc.y = fmaf(w2, h2.y, acc.y);
            acc.x = fmaf(w3, h3.x, acc.x); acc.y = fmaf(w3, h3.y, acc.y);
        }
        for (; j < m; j++) {
            const float w = s_w[j];
            const float2 h = *(const float2*)&g_h[(size_t)s_src[j]*HH + 2*t];
            acc.x = fmaf(w, h.x, acc.x);
            acc.y = fmaf(w, h.y, acc.y);
        }
    }

    float2 out;
    out.x = tanhf(acc.x + gcn_b[2*t]);
    out.y = tanhf(acc.y + gcn_b[2*t+1]);
    *(float2*)&g_z[(size_t)n*HH + 2*t] = out;
}

// ---------------- gate GEMM + combine + BN partial stats ----------------------
__global__ __launch_bounds__(256)
void gate_gemm_kernel(const float* __restrict__ A,     // g_z (tanh'd)
                      const float* __restrict__ B,     // gate_w
                      const float* __restrict__ bias,  // gate_b
                      float* __restrict__ out)
{
    __shared__ __align__(16) float As[KT][68];
    __shared__ __align__(16) float Bs[KT][68];
    __shared__ float redS[16][64];
    __shared__ float redQ[16][64];
    const int tid = threadIdx.x;
    const int tx = tid & 15, ty = tid >> 4;
    const int m0 = blockIdx.y * 64;
    const int n0 = blockIdx.x * 64;
    const int M = NN, K = HH;

    float acc[4][4] = {};

    for (int k0 = 0; k0 < K; k0 += KT) {
        #pragma unroll
        for (int p = 0; p < 8; p++) {
            const int idx = tid + p*256;
            const int m = idx >> 5, k = idx & 31;
            const int gm = m0 + m;
            As[k][m] = (gm < M) ? A[(size_t)gm*K + k0 + k] : 0.f;
        }
        {
            const int r = tid >> 4, q = tid & 15;
            #pragma unroll
            for (int p = 0; p < 2; p++) {
                const int k = r + p*16;
                *(float4*)&Bs[k][q*4] =
                    *(const float4*)&B[(size_t)(k0+k)*HH + n0 + q*4];
            }
        }
        __syncthreads();
        #pragma unroll
        for (int k = 0; k < KT; k++) {
            const float4 av = *(const float4*)&As[k][ty*4];
            const float4 bv = *(const float4*)&Bs[k][tx*4];
            const float a[4] = {av.x, av.y, av.z, av.w};
            const float b[4] = {bv.x, bv.y, bv.z, bv.w};
            #pragma unroll
            for (int i = 0; i < 4; i++)
                #pragma unroll
                for (int j = 0; j < 4; j++)
                    acc[i][j] = fmaf(a[i], b[j], acc[i][j]);
        }
        __syncthreads();
    }

    float cs[4] = {0.f,0.f,0.f,0.f};
    float cq[4] = {0.f,0.f,0.f,0.f};
    #pragma unroll
    for (int i = 0; i < 4; i++) {
        const int gm = m0 + ty*4 + i;
        if (gm >= M) continue;
        #pragma unroll
        for (int j = 0; j < 4; j++) {
            const int gn = n0 + tx*4 + j;
            const float g  = 1.f / (1.f + expf(-(acc[i][j] + bias[gn])));
            const float z  = A   [(size_t)gm*HH + gn];
            const float xl = g_xl[(size_t)gm*HH + gn];
            const float o  = fmaxf(fmaf(g, z - xl, xl), 0.f);
            out[(size_t)gm*HH + gn] = o;
            cs[j] += o;
            cq[j] += o*o;
        }
    }
    #pragma unroll
    for (int j = 0; j < 4; j++) {
        redS[ty][tx*4+j] = cs[j];
        redQ[ty][tx*4+j] = cq[j];
    }
    __syncthreads();
    if (tid < 64) {
        float s = 0.f, q = 0.f;
        #pragma unroll
        for (int r = 0; r < 16; r++) { s += redS[r][tid]; q += redQ[r][tid]; }
        atomicAdd(&g_colsum[n0 + tid], s);
        atomicAdd(&g_colsq [n0 + tid], q);
    }
}

// ---------------- batchnorm ----------------------------------------------------
__global__ void bn_final_kernel(const float* __restrict__ gamma,
                                const float* __restrict__ beta) {
    int j = blockIdx.x*blockDim.x + threadIdx.x;
    if (j < HH) {
        const float inv_n = 1.f / (float)NN;
        const float mean = g_colsum[j] * inv_n;
        const float var  = g_colsq[j] * inv_n - mean*mean;
        const float sc = rsqrtf(var + 1e-5f) * gamma[j];
        g_scale[j] = sc;
        g_shift[j] = beta[j] - mean*sc;
    }
}

__global__ void bn_apply_kernel(float* __restrict__ out) {
    int i = blockIdx.x*blockDim.x + threadIdx.x;
    if (i < NN*HH) {
        const int j = i & (HH-1);
        out[i] = fmaf(out[i], g_scale[j], g_shift[j]);
    }
}

// ---------------- launch ------------------------------------------------------
extern "C" void kernel_launch(void* const* d_in, const int* in_sizes, int n_in,
                              void* d_out, int out_size)
{
    const float* x      = (const float*)d_in[0];
    const int*   eidx   = (const int*)  d_in[1];
    const float* w1     = (const float*)d_in[2];
    const float* b1     = (const float*)d_in[3];
    const float* w2     = (const float*)d_in[4];
    const float* b2     = (const float*)d_in[5];
    const float* w3     = (const float*)d_in[6];
    const float* b3     = (const float*)d_in[7];
    const float* gcn_w  = (const float*)d_in[8];
    const float* gcn_b  = (const float*)d_in[9];
    const float* lin_w  = (const float*)d_in[10];
    const float* lin_b  = (const float*)d_in[11];
    const float* gate_w = (const float*)d_in[12];
    const float* gate_b = (const float*)d_in[13];
    const float* bn_g   = (const float*)d_in[14];
    const float* bn_b   = (const float*)d_in[15];
    float* out = (float*)d_out;

    const int* src = eidx;
    const int* dst = eidx + EE;

    float *p_feat, *p_z;
    cudaGetSymbolAddress((void**)&p_feat, g_feat);
    cudaGetSymbolAddress((void**)&p_z,    g_z);

    // 1) fused conv pipeline -> feat
    conv_feat_kernel<<<NN, 256>>>(x, w1, b1, w2, b2, w3, b3);

    // 2) CSR build: count, scan (+dinv), fill
    csr_init_kernel <<<(NN+255)/256, 256>>>();
    csr_count_kernel<<<(EE+255)/256, 256>>>(dst);
    csr_scan_kernel <<<1, 256>>>();
    csr_fill_kernel <<<(EE+255)/256, 256>>>(src, dst);

    // 3) dual GEMM: h = feat@gcn_w ; xl = feat@lin_w+b
    dual_gemm_kernel<<<dim3(HH/64, (NN+63)/64), 256>>>(p_feat, gcn_w, lin_w, lin_b);

    // 4) gather aggregation + tanh(+bias)  (atomic-free)
    gcn_gather_kernel<<<NN, 256>>>(gcn_b);

    // 5) gate GEMM + combine + relu + BN partial stats
    gate_gemm_kernel<<<dim3(HH/64, (NN+63)/64), 256>>>(p_z, gate_w, gate_b, out);

    // 6-7) batchnorm finalize + apply
    bn_final_kernel<<<(HH+255)/256, 256>>>(bn_g, bn_b);
    bn_apply_kernel<<<(NN*HH+255)/256, 256>>>(out);
}